// round 1
// baseline (speedup 1.0000x reference)
#include <cuda_runtime.h>
#include <math.h>

#define QLEN   1024
#define BSZ    4
#define DMODEL 1024
#define NHEAD  16
#define DHEAD  64
#define DINNER 4096
#define MEMLEN 1024
#define KLEN   2048
#define H3     (3 * DMODEL)   // 3072

// ---- static device scratch (no cudaMalloc allowed) ----
__device__ float g_heads[(size_t)KLEN * BSZ * H3];          // 8192 x 3072
__device__ float g_rk[(size_t)KLEN * DMODEL];               // 2048 x 1024
__device__ float g_AC[(size_t)BSZ * NHEAD * QLEN * KLEN];   // 64 x 1024 x 2048
__device__ float g_BD[(size_t)BSZ * NHEAD * QLEN * KLEN];
__device__ float g_av[(size_t)QLEN * BSZ * DMODEL];
__device__ float g_tmp[(size_t)QLEN * BSZ * DMODEL];
__device__ float g_out1[(size_t)QLEN * BSZ * DMODEL];
__device__ float g_ffh[(size_t)QLEN * BSZ * DINNER];        // 4096 x 4096

// ----------------------------------------------------------------------------
// Generic SGEMM: C[Mr,Nc] = Arows @ B (+bias)(+resid)(relu)
// A rows come from A for row < splitRow, else A2 (for the mems||w concat).
// 128x128 tile, 256 threads, 8x8 per thread, k-step 8.
// ----------------------------------------------------------------------------
__global__ __launch_bounds__(256) void sgemm_k(
    const float* __restrict__ A, const float* __restrict__ A2, int splitRow,
    const float* __restrict__ Bm, const float* __restrict__ bias,
    const float* __restrict__ resid, int doRelu,
    float* __restrict__ C, int Mr, int Nc, int Kd)
{
    __shared__ float As[8][132];
    __shared__ float Bs[8][132];
    const int tid = threadIdx.x;
    const int tx = tid & 15, ty = tid >> 4;
    const int bm = blockIdx.y * 128, bn = blockIdx.x * 128;

    float acc[8][8];
#pragma unroll
    for (int i = 0; i < 8; i++)
#pragma unroll
        for (int j = 0; j < 8; j++) acc[i][j] = 0.f;

    const int arow = tid >> 1, acol = (tid & 1) * 4;
    const int brow = tid >> 5, bcol = (tid & 31) * 4;
    const int gr = bm + arow;
    const float* aptr = (gr < splitRow) ? (A + (size_t)gr * Kd)
                                        : (A2 + (size_t)(gr - splitRow) * Kd);

    for (int k0 = 0; k0 < Kd; k0 += 8) {
        float4 av = *(const float4*)(aptr + k0 + acol);
        As[acol + 0][arow] = av.x;
        As[acol + 1][arow] = av.y;
        As[acol + 2][arow] = av.z;
        As[acol + 3][arow] = av.w;
        float4 bv = *(const float4*)(Bm + (size_t)(k0 + brow) * Nc + bn + bcol);
        *(float4*)&Bs[brow][bcol] = bv;
        __syncthreads();
#pragma unroll
        for (int k = 0; k < 8; k++) {
            float a[8], b[8];
            *(float4*)(&a[0]) = *(const float4*)(&As[k][ty * 4]);
            *(float4*)(&a[4]) = *(const float4*)(&As[k][64 + ty * 4]);
            *(float4*)(&b[0]) = *(const float4*)(&Bs[k][tx * 4]);
            *(float4*)(&b[4]) = *(const float4*)(&Bs[k][64 + tx * 4]);
#pragma unroll
            for (int i = 0; i < 8; i++)
#pragma unroll
                for (int j = 0; j < 8; j++)
                    acc[i][j] += a[i] * b[j];
        }
        __syncthreads();
    }

#pragma unroll
    for (int i = 0; i < 8; i++) {
        const int grow = bm + ((i < 4) ? (ty * 4 + i) : (64 + ty * 4 + (i - 4)));
#pragma unroll
        for (int jh = 0; jh < 2; jh++) {
            const int gcol = bn + jh * 64 + tx * 4;
            float4 v;
            v.x = acc[i][jh * 4 + 0];
            v.y = acc[i][jh * 4 + 1];
            v.z = acc[i][jh * 4 + 2];
            v.w = acc[i][jh * 4 + 3];
            if (bias) {
                const float4 bb = *(const float4*)(bias + gcol);
                v.x += bb.x; v.y += bb.y; v.z += bb.z; v.w += bb.w;
            }
            if (resid) {
                const float4 rv = *(const float4*)(resid + (size_t)grow * Nc + gcol);
                v.x += rv.x; v.y += rv.y; v.z += rv.z; v.w += rv.w;
            }
            if (doRelu) {
                v.x = fmaxf(v.x, 0.f); v.y = fmaxf(v.y, 0.f);
                v.z = fmaxf(v.z, 0.f); v.w = fmaxf(v.w, 0.f);
            }
            *(float4*)(C + (size_t)grow * Nc + gcol) = v;
        }
    }
}

// ----------------------------------------------------------------------------
// AC / BD score GEMMs per (b,n): C[i,j] = (q_i + bias_n) . key_j  over DH=64.
// isAC: key_j = k head from g_heads; else key_j = rk[j] (no b dependence).
// 64x64 output tile, 256 threads, 4x4 per thread, K=64 fully staged in smem.
// ----------------------------------------------------------------------------
__global__ __launch_bounds__(256) void score_gemm(
    const float* __restrict__ heads, const float* __restrict__ rk,
    const float* __restrict__ qbias, float* __restrict__ Cout, int isAC)
{
    const int bnidx = blockIdx.z;
    const int b = bnidx >> 4, n = bnidx & 15;
    const int i0 = blockIdx.y * 64, j0 = blockIdx.x * 64;
    __shared__ float Qs[64][65];
    __shared__ float Ks[64][65];
    const int tid = threadIdx.x;
    const int tx = tid & 15, ty = tid >> 4;

#pragma unroll
    for (int it = 0; it < 4; it++) {
        const int t = tid + it * 256;
        const int row = t >> 4, c4 = (t & 15) * 4;
        const float* qp = heads + ((size_t)(MEMLEN + i0 + row) * BSZ + b) * H3 + n * DHEAD + c4;
        float4 qv = *(const float4*)qp;
        const float4 bb = *(const float4*)(qbias + n * DHEAD + c4);
        Qs[row][c4 + 0] = qv.x + bb.x;
        Qs[row][c4 + 1] = qv.y + bb.y;
        Qs[row][c4 + 2] = qv.z + bb.z;
        Qs[row][c4 + 3] = qv.w + bb.w;
        float4 kv;
        if (isAC)
            kv = *(const float4*)(heads + ((size_t)(j0 + row) * BSZ + b) * H3 + DMODEL + n * DHEAD + c4);
        else
            kv = *(const float4*)(rk + (size_t)(j0 + row) * DMODEL + n * DHEAD + c4);
        Ks[row][c4 + 0] = kv.x;
        Ks[row][c4 + 1] = kv.y;
        Ks[row][c4 + 2] = kv.z;
        Ks[row][c4 + 3] = kv.w;
    }
    __syncthreads();

    float acc[4][4];
#pragma unroll
    for (int u = 0; u < 4; u++)
#pragma unroll
        for (int v = 0; v < 4; v++) acc[u][v] = 0.f;

#pragma unroll 8
    for (int k = 0; k < 64; k++) {
        float a[4], bv[4];
#pragma unroll
        for (int u = 0; u < 4; u++) a[u] = Qs[ty * 4 + u][k];
#pragma unroll
        for (int v = 0; v < 4; v++) bv[v] = Ks[tx * 4 + v][k];
#pragma unroll
        for (int u = 0; u < 4; u++)
#pragma unroll
            for (int v = 0; v < 4; v++) acc[u][v] += a[u] * bv[v];
    }

#pragma unroll
    for (int u = 0; u < 4; u++) {
        float4 v;
        v.x = acc[u][0]; v.y = acc[u][1]; v.z = acc[u][2]; v.w = acc[u][3];
        *(float4*)(Cout + ((size_t)bnidx * QLEN + i0 + ty * 4 + u) * KLEN + j0 + tx * 4) = v;
    }
}

// ----------------------------------------------------------------------------
// Fused rel-shift + mask + scale + softmax, one block per (i, b*NH+n) row.
// P written in place over AC. BD read with shifted column j - i + QLEN - 1.
// ----------------------------------------------------------------------------
__device__ __forceinline__ float warpMax(float v) {
#pragma unroll
    for (int o = 16; o; o >>= 1) v = fmaxf(v, __shfl_xor_sync(0xffffffffu, v, o));
    return v;
}
__device__ __forceinline__ float warpSum(float v) {
#pragma unroll
    for (int o = 16; o; o >>= 1) v += __shfl_xor_sync(0xffffffffu, v, o);
    return v;
}

__global__ __launch_bounds__(256) void softmax_k(
    const float* __restrict__ AC, const float* __restrict__ BD, float* __restrict__ P)
{
    __shared__ float s[KLEN];
    __shared__ float red[8];
    const int i = blockIdx.x;
    const int bnidx = blockIdx.y;
    const int tid = threadIdx.x;
    const float* ac = AC + ((size_t)bnidx * QLEN + i) * KLEN;
    const float* bd = BD + ((size_t)bnidx * QLEN + i) * KLEN;
    const int jmax = i + MEMLEN;  // valid: j <= jmax

    float lmax = -1e30f;
    for (int j = tid; j < KLEN; j += 256) {
        float v = -1e30f;
        if (j <= jmax) v = (ac[j] + bd[j - i + (QLEN - 1)]) * 0.125f;
        s[j] = v;
        lmax = fmaxf(lmax, v);
    }
    // block max
    float wm = warpMax(lmax);
    if ((tid & 31) == 0) red[tid >> 5] = wm;
    __syncthreads();
    if (tid < 32) {
        float v = (tid < 8) ? red[tid] : -1e30f;
        v = warpMax(v);
        if (tid == 0) red[0] = v;
    }
    __syncthreads();
    const float m = red[0];
    __syncthreads();

    float lsum = 0.f;
    for (int j = tid; j < KLEN; j += 256) {
        float p = (j <= jmax) ? __expf(s[j] - m) : 0.f;
        s[j] = p;
        lsum += p;
    }
    float ws = warpSum(lsum);
    if ((tid & 31) == 0) red[tid >> 5] = ws;
    __syncthreads();
    if (tid < 32) {
        float v = (tid < 8) ? red[tid] : 0.f;
        v = warpSum(v);
        if (tid == 0) red[0] = v;
    }
    __syncthreads();
    const float inv = 1.f / red[0];

    float* outp = P + ((size_t)bnidx * QLEN + i) * KLEN;
    for (int j = tid; j < KLEN; j += 256) outp[j] = s[j] * inv;
}

// ----------------------------------------------------------------------------
// attn_vec = P @ V per (b,n). 64 queries x 64 (=DH) per block, 32 k-tiles.
// ----------------------------------------------------------------------------
__global__ __launch_bounds__(256) void pv_gemm(
    const float* __restrict__ P, const float* __restrict__ heads, float* __restrict__ av)
{
    const int bnidx = blockIdx.y;
    const int b = bnidx >> 4, n = bnidx & 15;
    const int i0 = blockIdx.x * 64;
    __shared__ float Ps[64][65];
    __shared__ float Vs[64][65];
    const int tid = threadIdx.x;
    const int tx = tid & 15, ty = tid >> 4;

    float acc[4][4];
#pragma unroll
    for (int u = 0; u < 4; u++)
#pragma unroll
        for (int v = 0; v < 4; v++) acc[u][v] = 0.f;

    for (int jt = 0; jt < 32; jt++) {
        const int j0 = jt * 64;
#pragma unroll
        for (int it = 0; it < 4; it++) {
            const int t = tid + it * 256;
            const int row = t >> 4, c4 = (t & 15) * 4;
            float4 pv = *(const float4*)(P + ((size_t)bnidx * QLEN + i0 + row) * KLEN + j0 + c4);
            Ps[row][c4 + 0] = pv.x;
            Ps[row][c4 + 1] = pv.y;
            Ps[row][c4 + 2] = pv.z;
            Ps[row][c4 + 3] = pv.w;
            float4 vv = *(const float4*)(heads + ((size_t)(j0 + row) * BSZ + b) * H3 + 2 * DMODEL + n * DHEAD + c4);
            Vs[row][c4 + 0] = vv.x;
            Vs[row][c4 + 1] = vv.y;
            Vs[row][c4 + 2] = vv.z;
            Vs[row][c4 + 3] = vv.w;
        }
        __syncthreads();
#pragma unroll 8
        for (int k = 0; k < 64; k++) {
            float a[4], bv[4];
#pragma unroll
            for (int u = 0; u < 4; u++) a[u] = Ps[ty * 4 + u][k];
#pragma unroll
            for (int v = 0; v < 4; v++) bv[v] = Vs[k][tx * 4 + v];
#pragma unroll
            for (int u = 0; u < 4; u++)
#pragma unroll
                for (int v = 0; v < 4; v++) acc[u][v] += a[u] * bv[v];
        }
        __syncthreads();
    }

#pragma unroll
    for (int u = 0; u < 4; u++) {
        float4 v;
        v.x = acc[u][0]; v.y = acc[u][1]; v.z = acc[u][2]; v.w = acc[u][3];
        *(float4*)(av + ((size_t)(i0 + ty * 4 + u) * BSZ + b) * DMODEL + n * DHEAD + tx * 4) = v;
    }
}

// ----------------------------------------------------------------------------
// Row LayerNorm over D=1024 (one block per row, 4 elems/thread).
// ----------------------------------------------------------------------------
__global__ __launch_bounds__(256) void ln_k(
    const float* __restrict__ X, const float* __restrict__ gam,
    const float* __restrict__ bet, float* __restrict__ Y)
{
    __shared__ float red[8];
    const size_t row = blockIdx.x;
    const int tid = threadIdx.x;
    const float4 v = *(const float4*)(X + row * DMODEL + tid * 4);
    float s = v.x + v.y + v.z + v.w;
    float q = v.x * v.x + v.y * v.y + v.z * v.z + v.w * v.w;

    float ws = warpSum(s);
    if ((tid & 31) == 0) red[tid >> 5] = ws;
    __syncthreads();
    if (tid < 32) {
        float t = (tid < 8) ? red[tid] : 0.f;
        t = warpSum(t);
        if (tid == 0) red[0] = t;
    }
    __syncthreads();
    const float mu = red[0] * (1.f / DMODEL);
    __syncthreads();

    float wq = warpSum(q);
    if ((tid & 31) == 0) red[tid >> 5] = wq;
    __syncthreads();
    if (tid < 32) {
        float t = (tid < 8) ? red[tid] : 0.f;
        t = warpSum(t);
        if (tid == 0) red[0] = t;
    }
    __syncthreads();
    const float var = red[0] * (1.f / DMODEL) - mu * mu;
    const float rs = rsqrtf(var + 1e-5f);

    const float4 gv = *(const float4*)(gam + tid * 4);
    const float4 bv = *(const float4*)(bet + tid * 4);
    float4 o;
    o.x = (v.x - mu) * rs * gv.x + bv.x;
    o.y = (v.y - mu) * rs * gv.y + bv.y;
    o.z = (v.z - mu) * rs * gv.z + bv.z;
    o.w = (v.w - mu) * rs * gv.w + bv.w;
    *(float4*)(Y + row * DMODEL + tid * 4) = o;
}

// ----------------------------------------------------------------------------
extern "C" void kernel_launch(void* const* d_in, const int* in_sizes, int n_in,
                              void* d_out, int out_size)
{
    (void)in_sizes; (void)n_in; (void)out_size;
    const float* w       = (const float*)d_in[0];
    const float* r       = (const float*)d_in[1];
    const float* mems    = (const float*)d_in[2];
    const float* qkv_w   = (const float*)d_in[3];
    const float* r_net_w = (const float*)d_in[4];
    const float* o_w     = (const float*)d_in[5];
    const float* rwb     = (const float*)d_in[6];
    const float* rrb     = (const float*)d_in[7];
    const float* ln1g    = (const float*)d_in[8];
    const float* ln1b    = (const float*)d_in[9];
    const float* ffw1    = (const float*)d_in[10];
    const float* ffb1    = (const float*)d_in[11];
    const float* ffw2    = (const float*)d_in[12];
    const float* ffb2    = (const float*)d_in[13];
    const float* ln2g    = (const float*)d_in[14];
    const float* ln2b    = (const float*)d_in[15];
    float* out = (float*)d_out;

    float *heads, *rk, *AC, *BD, *av, *tmp, *out1, *ffh;
    cudaGetSymbolAddress((void**)&heads, g_heads);
    cudaGetSymbolAddress((void**)&rk,    g_rk);
    cudaGetSymbolAddress((void**)&AC,    g_AC);
    cudaGetSymbolAddress((void**)&BD,    g_BD);
    cudaGetSymbolAddress((void**)&av,    g_av);
    cudaGetSymbolAddress((void**)&tmp,   g_tmp);
    cudaGetSymbolAddress((void**)&out1,  g_out1);
    cudaGetSymbolAddress((void**)&ffh,   g_ffh);

    const dim3 blk(256);
    const int NOSPLIT = 1 << 30;

    // 1) heads = concat(mems, w) @ qkv_w          [8192 x 3072 x 1024]
    sgemm_k<<<dim3(H3 / 128, (KLEN * BSZ) / 128), blk>>>(
        mems, w, MEMLEN * BSZ, qkv_w, nullptr, nullptr, 0,
        heads, KLEN * BSZ, H3, DMODEL);

    // 2) rk = r @ r_net_w                          [2048 x 1024 x 1024]
    sgemm_k<<<dim3(DMODEL / 128, KLEN / 128), blk>>>(
        r, r, NOSPLIT, r_net_w, nullptr, nullptr, 0,
        rk, KLEN, DMODEL, DMODEL);

    // 3) AC[i,j] = (q+rwb).k ; 4) BD_pre[i,c] = (q+rrb).rk
    score_gemm<<<dim3(KLEN / 64, QLEN / 64, BSZ * NHEAD), blk>>>(heads, rk, rwb, AC, 1);
    score_gemm<<<dim3(KLEN / 64, QLEN / 64, BSZ * NHEAD), blk>>>(heads, rk, rrb, BD, 0);

    // 5) shift + mask + scale + softmax -> P (in place over AC)
    softmax_k<<<dim3(QLEN, BSZ * NHEAD), blk>>>(AC, BD, AC);

    // 6) attn_vec = P @ V
    pv_gemm<<<dim3(QLEN / 64, BSZ * NHEAD), blk>>>(AC, heads, av);

    // 7) attn_out = av @ o_w + w (residual)        [4096 x 1024 x 1024]
    sgemm_k<<<dim3(DMODEL / 128, (QLEN * BSZ) / 128), blk>>>(
        av, av, NOSPLIT, o_w, nullptr, w, 0,
        tmp, QLEN * BSZ, DMODEL, DMODEL);

    // 8) LN1
    ln_k<<<QLEN * BSZ, blk>>>(tmp, ln1g, ln1b, out1);

    // 9) ffh = relu(out1 @ ff_w1 + b1)             [4096 x 4096 x 1024]
    sgemm_k<<<dim3(DINNER / 128, (QLEN * BSZ) / 128), blk>>>(
        out1, out1, NOSPLIT, ffw1, ffb1, nullptr, 1,
        ffh, QLEN * BSZ, DINNER, DMODEL);

    // 10) tmp = ffh @ ff_w2 + b2 + out1            [4096 x 1024 x 4096]
    sgemm_k<<<dim3(DMODEL / 128, (QLEN * BSZ) / 128), blk>>>(
        ffh, ffh, NOSPLIT, ffw2, ffb2, out1, 0,
        tmp, QLEN * BSZ, DMODEL, DINNER);

    // 11) LN2 -> output
    ln_k<<<QLEN * BSZ, blk>>>(tmp, ln2g, ln2b, out);
}

// round 3
// speedup vs baseline: 1.5497x; 1.5497x over previous
#include <cuda_runtime.h>
#include <math.h>
#include <stdint.h>

#define QLEN   1024
#define BSZ    4
#define DMODEL 1024
#define NHEAD  16
#define DHEAD  64
#define DINNER 4096
#define MEMLEN 1024
#define KLEN   2048
#define H3     (3 * DMODEL)   // 3072
#define QK     ((long long)QLEN * KLEN)

// ---- static device scratch (no cudaMalloc allowed) ----
__device__ float g_heads[(size_t)KLEN * BSZ * H3];          // 8192 x 3072
__device__ float g_rk[(size_t)KLEN * DMODEL];               // 2048 x 1024
__device__ float g_AC[(size_t)BSZ * NHEAD * QLEN * KLEN];   // 64 x 1024 x 2048
__device__ float g_BD[(size_t)BSZ * NHEAD * QLEN * KLEN];
__device__ float g_av[(size_t)QLEN * BSZ * DMODEL];
__device__ float g_tmp[(size_t)QLEN * BSZ * DMODEL];
__device__ float g_out1[(size_t)QLEN * BSZ * DMODEL];
__device__ float g_ffh[(size_t)QLEN * BSZ * DINNER];        // 4096 x 4096

__device__ __forceinline__ uint32_t f2tf32(float x) {
    uint32_t u;
    asm("cvt.rna.tf32.f32 %0, %1;" : "=r"(u) : "f"(x));
    return u;
}

#define MMA_TF32(acc, av, bv)                                               \
    asm volatile(                                                           \
        "mma.sync.aligned.m16n8k8.row.col.f32.tf32.tf32.f32 "               \
        "{%0,%1,%2,%3}, {%4,%5,%6,%7}, {%8,%9}, {%0,%1,%2,%3};"             \
        : "+f"(acc[0]), "+f"(acc[1]), "+f"(acc[2]), "+f"(acc[3])            \
        : "r"(av[0]), "r"(av[1]), "r"(av[2]), "r"(av[3]),                   \
          "r"(bv[0]), "r"(bv[1]))

// ----------------------------------------------------------------------------
// Generic batched strided tf32 tensor-core GEMM.
//   C[batch][M,N] (+cbias)(+resid)(relu) = Arows @ B   (BT=0: B row-major [K,N],
//                                                       BT=1: B row-major [N,K], used transposed)
// A rows split across A/A2 at splitRow (for the mems||w concat).
// Per-batch offsets: off = (batch>>4)*Hi + (batch&15)*Lo for A, B, C.
// Optional abias added to A elements: abias[(batch&15)*abLo + k].
// Block tile 128x128, 8 warps (2x4) of 64x32, k-step 16, double-buffered smem.
// ----------------------------------------------------------------------------
template <int BT>
__global__ __launch_bounds__(256) void mma_gemm(
    const float* __restrict__ A, const float* __restrict__ A2, int splitRow,
    long long aRow, long long aHi, long long aLo,
    const float* __restrict__ abias, int abLo,
    const float* __restrict__ B, long long bRow, long long bHi, long long bLo,
    const float* __restrict__ cbias, const float* __restrict__ resid, int doRelu,
    float* __restrict__ C, long long cRow, long long cHi, long long cLo,
    int M, int N, int Kd)
{
    __shared__ uint32_t As[2][2560];   // [m][20] (16 k + 4 pad)
    __shared__ uint32_t Bs[2][2560];   // BT: [n][20]; !BT: [k][136]

    const int tid  = threadIdx.x;
    const int warp = tid >> 5, lane = tid & 31;
    const int lr = lane >> 2, lc = lane & 3;
    const int bm = blockIdx.y * 128, bn = blockIdx.x * 128;
    const int bh = blockIdx.z >> 4, bl = blockIdx.z & 15;
    const long long aOff = (long long)bh * aHi + (long long)bl * aLo;
    const long long bOff = (long long)bh * bHi + (long long)bl * bLo;
    const long long cOff = (long long)bh * cHi + (long long)bl * cLo;
    const int wm = (warp & 1) * 64;
    const int wn = (warp >> 1) * 32;

    float acc[4][4][4];
#pragma unroll
    for (int mt = 0; mt < 4; mt++)
#pragma unroll
        for (int nt = 0; nt < 4; nt++)
#pragma unroll
            for (int q = 0; q < 4; q++) acc[mt][nt][q] = 0.f;

    const int ar  = tid >> 2;          // 0..63 (row within 64 for A / Bt)
    const int akc = (tid & 3) << 2;    // 0,4,8,12
    const int bkr = tid >> 5;          // 0..7 (k row for !BT B loader)
    const int bc  = (tid & 31) << 2;   // 0..124

    float4 aS[2], bS[2];

    auto gload = [&](int kt) {
        const int k0 = kt * 16;
#pragma unroll
        for (int h = 0; h < 2; h++) {
            const int row = bm + ar + h * 64;
            const float* ap = (row < splitRow)
                ? (A  + aOff + (long long)row * aRow)
                : (A2 + aOff + (long long)(row - splitRow) * aRow);
            float4 v = *(const float4*)(ap + k0 + akc);
            if (abias) {
                const float4 bb = *(const float4*)(abias + bl * abLo + k0 + akc);
                v.x += bb.x; v.y += bb.y; v.z += bb.z; v.w += bb.w;
            }
            aS[h] = v;
        }
        if (BT) {
#pragma unroll
            for (int h = 0; h < 2; h++) {
                const int nrow = bn + ar + h * 64;
                float4 v = make_float4(0.f, 0.f, 0.f, 0.f);
                if (nrow < N)
                    v = *(const float4*)(B + bOff + (long long)nrow * bRow + k0 + akc);
                bS[h] = v;
            }
        } else {
            const int col = bn + bc;
#pragma unroll
            for (int h = 0; h < 2; h++) {
                float4 v = make_float4(0.f, 0.f, 0.f, 0.f);
                if (col < N)
                    v = *(const float4*)(B + bOff + (long long)(k0 + bkr + h * 8) * bRow + col);
                bS[h] = v;
            }
        }
    };

    auto sstore = [&](int buf) {
#pragma unroll
        for (int h = 0; h < 2; h++) {
            uint32_t* p = &As[buf][(ar + h * 64) * 20 + akc];
            *(uint4*)p = make_uint4(f2tf32(aS[h].x), f2tf32(aS[h].y),
                                    f2tf32(aS[h].z), f2tf32(aS[h].w));
        }
        if (BT) {
#pragma unroll
            for (int h = 0; h < 2; h++) {
                uint32_t* p = &Bs[buf][(ar + h * 64) * 20 + akc];
                *(uint4*)p = make_uint4(f2tf32(bS[h].x), f2tf32(bS[h].y),
                                        f2tf32(bS[h].z), f2tf32(bS[h].w));
            }
        } else {
#pragma unroll
            for (int h = 0; h < 2; h++) {
                uint32_t* p = &Bs[buf][(bkr + h * 8) * 136 + bc];
                *(uint4*)p = make_uint4(f2tf32(bS[h].x), f2tf32(bS[h].y),
                                        f2tf32(bS[h].z), f2tf32(bS[h].w));
            }
        }
    };

    auto compute = [&](int buf) {
#pragma unroll
        for (int kk = 0; kk < 16; kk += 8) {
            uint32_t af[4][4], bf[4][2];
#pragma unroll
            for (int mt = 0; mt < 4; mt++) {
                const int m0 = wm + mt * 16 + lr;
                af[mt][0] = As[buf][m0 * 20 + kk + lc];
                af[mt][1] = As[buf][(m0 + 8) * 20 + kk + lc];
                af[mt][2] = As[buf][m0 * 20 + kk + 4 + lc];
                af[mt][3] = As[buf][(m0 + 8) * 20 + kk + 4 + lc];
            }
#pragma unroll
            for (int nt = 0; nt < 4; nt++) {
                const int n0 = wn + nt * 8 + lr;
                if (BT) {
                    bf[nt][0] = Bs[buf][n0 * 20 + kk + lc];
                    bf[nt][1] = Bs[buf][n0 * 20 + kk + 4 + lc];
                } else {
                    bf[nt][0] = Bs[buf][(kk + lc) * 136 + n0];
                    bf[nt][1] = Bs[buf][(kk + 4 + lc) * 136 + n0];
                }
            }
#pragma unroll
            for (int mt = 0; mt < 4; mt++)
#pragma unroll
                for (int nt = 0; nt < 4; nt++)
                    MMA_TF32(acc[mt][nt], af[mt], bf[nt]);
        }
    };

    const int nk = Kd >> 4;
    gload(0);
    sstore(0);
    __syncthreads();
    for (int kt = 0; kt < nk; kt++) {
        const int buf = kt & 1;
        if (kt + 1 < nk) gload(kt + 1);
        compute(buf);
        if (kt + 1 < nk) sstore(buf ^ 1);
        __syncthreads();
    }

    // epilogue
#pragma unroll
    for (int mt = 0; mt < 4; mt++) {
#pragma unroll
        for (int nt = 0; nt < 4; nt++) {
            const int col = bn + wn + nt * 8 + lc * 2;
            if (col >= N) continue;
#pragma unroll
            for (int half = 0; half < 2; half++) {
                const int row = bm + wm + mt * 16 + lr + half * 8;
                float v0 = acc[mt][nt][half * 2 + 0];
                float v1 = acc[mt][nt][half * 2 + 1];
                if (cbias) { v0 += cbias[col]; v1 += cbias[col + 1]; }
                if (resid) {
                    const float* rp = resid + cOff + (long long)row * cRow + col;
                    v0 += rp[0]; v1 += rp[1];
                }
                if (doRelu) { v0 = fmaxf(v0, 0.f); v1 = fmaxf(v1, 0.f); }
                float* cp = C + cOff + (long long)row * cRow + col;
                cp[0] = v0; cp[1] = v1;
            }
        }
    }
}

// ----------------------------------------------------------------------------
// Fused rel-shift + mask + scale + softmax, one block per (i, b*NH+n) row.
// ----------------------------------------------------------------------------
__device__ __forceinline__ float warpMax(float v) {
#pragma unroll
    for (int o = 16; o; o >>= 1) v = fmaxf(v, __shfl_xor_sync(0xffffffffu, v, o));
    return v;
}
__device__ __forceinline__ float warpSum(float v) {
#pragma unroll
    for (int o = 16; o; o >>= 1) v += __shfl_xor_sync(0xffffffffu, v, o);
    return v;
}

__global__ __launch_bounds__(256) void softmax_k(
    const float* __restrict__ AC, const float* __restrict__ BD, float* __restrict__ P)
{
    __shared__ float s[KLEN];
    __shared__ float red[8];
    const int i = blockIdx.x;
    const int bnidx = blockIdx.y;
    const int tid = threadIdx.x;
    const float* ac = AC + ((size_t)bnidx * QLEN + i) * KLEN;
    const float* bd = BD + ((size_t)bnidx * QLEN + i) * KLEN;
    const int jmax = i + MEMLEN;  // valid: j <= jmax

    float lmax = -1e30f;
    for (int j = tid; j < KLEN; j += 256) {
        float v = -1e30f;
        if (j <= jmax) v = (ac[j] + bd[j - i + (QLEN - 1)]) * 0.125f;
        s[j] = v;
        lmax = fmaxf(lmax, v);
    }
    float wm = warpMax(lmax);
    if ((tid & 31) == 0) red[tid >> 5] = wm;
    __syncthreads();
    if (tid < 32) {
        float v = (tid < 8) ? red[tid] : -1e30f;
        v = warpMax(v);
        if (tid == 0) red[0] = v;
    }
    __syncthreads();
    const float m = red[0];
    __syncthreads();

    float lsum = 0.f;
    for (int j = tid; j < KLEN; j += 256) {
        float p = (j <= jmax) ? __expf(s[j] - m) : 0.f;
        s[j] = p;
        lsum += p;
    }
    float ws = warpSum(lsum);
    if ((tid & 31) == 0) red[tid >> 5] = ws;
    __syncthreads();
    if (tid < 32) {
        float v = (tid < 8) ? red[tid] : 0.f;
        v = warpSum(v);
        if (tid == 0) red[0] = v;
    }
    __syncthreads();
    const float inv = 1.f / red[0];

    float* outp = P + ((size_t)bnidx * QLEN + i) * KLEN;
    for (int j = tid; j < KLEN; j += 256) outp[j] = s[j] * inv;
}

// ----------------------------------------------------------------------------
// Row LayerNorm over D=1024 (one block per row, 4 elems/thread).
// ----------------------------------------------------------------------------
__global__ __launch_bounds__(256) void ln_k(
    const float* __restrict__ X, const float* __restrict__ gam,
    const float* __restrict__ bet, float* __restrict__ Y)
{
    __shared__ float red[8];
    const size_t row = blockIdx.x;
    const int tid = threadIdx.x;
    const float4 v = *(const float4*)(X + row * DMODEL + tid * 4);
    float s = v.x + v.y + v.z + v.w;
    float q = v.x * v.x + v.y * v.y + v.z * v.z + v.w * v.w;

    float ws = warpSum(s);
    if ((tid & 31) == 0) red[tid >> 5] = ws;
    __syncthreads();
    if (tid < 32) {
        float t = (tid < 8) ? red[tid] : 0.f;
        t = warpSum(t);
        if (tid == 0) red[0] = t;
    }
    __syncthreads();
    const float mu = red[0] * (1.f / DMODEL);
    __syncthreads();

    float wq = warpSum(q);
    if ((tid & 31) == 0) red[tid >> 5] = wq;
    __syncthreads();
    if (tid < 32) {
        float t = (tid < 8) ? red[tid] : 0.f;
        t = warpSum(t);
        if (tid == 0) red[0] = t;
    }
    __syncthreads();
    const float var = red[0] * (1.f / DMODEL) - mu * mu;
    const float rs = rsqrtf(var + 1e-5f);

    const float4 gv = *(const float4*)(gam + tid * 4);
    const float4 bv = *(const float4*)(bet + tid * 4);
    float4 o;
    o.x = (v.x - mu) * rs * gv.x + bv.x;
    o.y = (v.y - mu) * rs * gv.y + bv.y;
    o.z = (v.z - mu) * rs * gv.z + bv.z;
    o.w = (v.w - mu) * rs * gv.w + bv.w;
    *(float4*)(Y + row * DMODEL + tid * 4) = o;
}

// ----------------------------------------------------------------------------
extern "C" void kernel_launch(void* const* d_in, const int* in_sizes, int n_in,
                              void* d_out, int out_size)
{
    (void)in_sizes; (void)n_in; (void)out_size;
    const float* w       = (const float*)d_in[0];
    const float* r       = (const float*)d_in[1];
    const float* mems    = (const float*)d_in[2];
    const float* qkv_w   = (const float*)d_in[3];
    const float* r_net_w = (const float*)d_in[4];
    const float* o_w     = (const float*)d_in[5];
    const float* rwb     = (const float*)d_in[6];
    const float* rrb     = (const float*)d_in[7];
    const float* ln1g    = (const float*)d_in[8];
    const float* ln1b    = (const float*)d_in[9];
    const float* ffw1    = (const float*)d_in[10];
    const float* ffb1    = (const float*)d_in[11];
    const float* ffw2    = (const float*)d_in[12];
    const float* ffb2    = (const float*)d_in[13];
    const float* ln2g    = (const float*)d_in[14];
    const float* ln2b    = (const float*)d_in[15];
    float* out = (float*)d_out;

    float *heads, *rk, *AC, *BD, *av, *tmp, *out1, *ffh;
    cudaGetSymbolAddress((void**)&heads, g_heads);
    cudaGetSymbolAddress((void**)&rk,    g_rk);
    cudaGetSymbolAddress((void**)&AC,    g_AC);
    cudaGetSymbolAddress((void**)&BD,    g_BD);
    cudaGetSymbolAddress((void**)&av,    g_av);
    cudaGetSymbolAddress((void**)&tmp,   g_tmp);
    cudaGetSymbolAddress((void**)&out1,  g_out1);
    cudaGetSymbolAddress((void**)&ffh,   g_ffh);

    const dim3 blk(256);
    const int BIG = 1 << 30;
    const float* qbase = heads + (size_t)MEMLEN * BSZ * H3;  // query rows

    // 1) heads = concat(mems, w) @ qkv_w          [8192 x 3072 x 1024]
    mma_gemm<0><<<dim3(H3 / 128, (KLEN * BSZ) / 128, 1), blk>>>(
        mems, w, MEMLEN * BSZ, DMODEL, 0, 0, nullptr, 0,
        qkv_w, H3, 0, 0, nullptr, nullptr, 0,
        heads, H3, 0, 0, KLEN * BSZ, H3, DMODEL);

    // 2) rk = r @ r_net_w                          [2048 x 1024 x 1024]
    mma_gemm<0><<<dim3(DMODEL / 128, KLEN / 128, 1), blk>>>(
        r, r, BIG, DMODEL, 0, 0, nullptr, 0,
        r_net_w, DMODEL, 0, 0, nullptr, nullptr, 0,
        rk, DMODEL, 0, 0, KLEN, DMODEL, DMODEL);

    // 3) AC[bn][i][j] = (q_i + rwb_n) . k_j        batched, K=64
    mma_gemm<1><<<dim3(KLEN / 128, QLEN / 128, BSZ * NHEAD), blk>>>(
        qbase, qbase, BIG, BSZ * H3, H3, DHEAD, rwb, DHEAD,
        heads + DMODEL, BSZ * H3, H3, DHEAD, nullptr, nullptr, 0,
        AC, KLEN, 16 * QK, QK, QLEN, KLEN, DHEAD);

    // 4) BD_pre[bn][i][c] = (q_i + rrb_n) . rk_c   batched, K=64
    mma_gemm<1><<<dim3(KLEN / 128, QLEN / 128, BSZ * NHEAD), blk>>>(
        qbase, qbase, BIG, BSZ * H3, H3, DHEAD, rrb, DHEAD,
        rk, DMODEL, 0, DHEAD, nullptr, nullptr, 0,
        BD, KLEN, 16 * QK, QK, QLEN, KLEN, DHEAD);

    // 5) shift + mask + scale + softmax -> P (in place over AC)
    softmax_k<<<dim3(QLEN, BSZ * NHEAD), blk>>>(AC, BD, AC);

    // 6) attn_vec = P @ V                          batched, N=64, K=2048
    mma_gemm<0><<<dim3(1, QLEN / 128, BSZ * NHEAD), blk>>>(
        AC, AC, BIG, KLEN, 16 * QK, QK, nullptr, 0,
        heads + 2 * DMODEL, BSZ * H3, H3, DHEAD, nullptr, nullptr, 0,
        av, BSZ * DMODEL, DMODEL, DHEAD, QLEN, DHEAD, KLEN);

    // 7) attn_out = av @ o_w + w (residual)        [4096 x 1024 x 1024]
    mma_gemm<0><<<dim3(DMODEL / 128, (QLEN * BSZ) / 128, 1), blk>>>(
        av, av, BIG, DMODEL, 0, 0, nullptr, 0,
        o_w, DMODEL, 0, 0, nullptr, w, 0,
        tmp, DMODEL, 0, 0, QLEN * BSZ, DMODEL, DMODEL);

    // 8) LN1
    ln_k<<<QLEN * BSZ, blk>>>(tmp, ln1g, ln1b, out1);

    // 9) ffh = relu(out1 @ ff_w1 + b1)             [4096 x 4096 x 1024]
    mma_gemm<0><<<dim3(DINNER / 128, (QLEN * BSZ) / 128, 1), blk>>>(
        out1, out1, BIG, DMODEL, 0, 0, nullptr, 0,
        ffw1, DINNER, 0, 0, ffb1, nullptr, 1,
        ffh, DINNER, 0, 0, QLEN * BSZ, DINNER, DMODEL);

    // 10) tmp = ffh @ ff_w2 + b2 + out1            [4096 x 1024 x 4096]
    mma_gemm<0><<<dim3(DMODEL / 128, (QLEN * BSZ) / 128, 1), blk>>>(
        ffh, ffh, BIG, DINNER, 0, 0, nullptr, 0,
        ffw2, DMODEL, 0, 0, ffb2, out1, 0,
        tmp, DMODEL, 0, 0, QLEN * BSZ, DMODEL, DINNER);

    // 11) LN2 -> output
    ln_k<<<QLEN * BSZ, blk>>>(tmp, ln2g, ln2b, out);
}

// round 4
// speedup vs baseline: 2.8286x; 1.8253x over previous
#include <cuda_runtime.h>
#include <math.h>
#include <stdint.h>

#define QLEN   1024
#define BSZ    4
#define DMODEL 1024
#define NHEAD  16
#define DHEAD  64
#define DINNER 4096
#define MEMLEN 1024
#define KLEN   2048
#define H3     (3 * DMODEL)   // 3072
#define QK     ((long long)QLEN * KLEN)

// ---- static device scratch (no cudaMalloc allowed) ----
__device__ float g_heads[(size_t)KLEN * BSZ * H3];          // 8192 x 3072
__device__ float g_rk[(size_t)KLEN * DMODEL];               // 2048 x 1024
__device__ float g_BD[(size_t)BSZ * NHEAD * QLEN * KLEN];
__device__ float g_av[(size_t)QLEN * BSZ * DMODEL];
__device__ float g_tmp[(size_t)QLEN * BSZ * DMODEL];
__device__ float g_out1[(size_t)QLEN * BSZ * DMODEL];
__device__ float g_ffh[(size_t)QLEN * BSZ * DINNER];        // 4096 x 4096

__device__ __forceinline__ uint32_t f2tf32(float x) {
    uint32_t u;
    asm("cvt.rna.tf32.f32 %0, %1;" : "=r"(u) : "f"(x));
    return u;
}

#define MMA_TF32(acc, av, bv)                                               \
    asm volatile(                                                           \
        "mma.sync.aligned.m16n8k8.row.col.f32.tf32.tf32.f32 "               \
        "{%0,%1,%2,%3}, {%4,%5,%6,%7}, {%8,%9}, {%0,%1,%2,%3};"             \
        : "+f"(acc[0]), "+f"(acc[1]), "+f"(acc[2]), "+f"(acc[3])            \
        : "r"(av[0]), "r"(av[1]), "r"(av[2]), "r"(av[3]),                   \
          "r"(bv[0]), "r"(bv[1]))

// ----------------------------------------------------------------------------
// Generic batched strided tf32 tensor-core GEMM (unchanged from R1).
// ----------------------------------------------------------------------------
template <int BT>
__global__ __launch_bounds__(256) void mma_gemm(
    const float* __restrict__ A, const float* __restrict__ A2, int splitRow,
    long long aRow, long long aHi, long long aLo,
    const float* __restrict__ abias, int abLo,
    const float* __restrict__ B, long long bRow, long long bHi, long long bLo,
    const float* __restrict__ cbias, const float* __restrict__ resid, int doRelu,
    float* __restrict__ C, long long cRow, long long cHi, long long cLo,
    int M, int N, int Kd)
{
    __shared__ uint32_t As[2][2560];   // [m][20] (16 k + 4 pad)
    __shared__ uint32_t Bs[2][2560];   // BT: [n][20]; !BT: [k][136]

    const int tid  = threadIdx.x;
    const int warp = tid >> 5, lane = tid & 31;
    const int lr = lane >> 2, lc = lane & 3;
    const int bm = blockIdx.y * 128, bn = blockIdx.x * 128;
    const int bh = blockIdx.z >> 4, bl = blockIdx.z & 15;
    const long long aOff = (long long)bh * aHi + (long long)bl * aLo;
    const long long bOff = (long long)bh * bHi + (long long)bl * bLo;
    const long long cOff = (long long)bh * cHi + (long long)bl * cLo;
    const int wm = (warp & 1) * 64;
    const int wn = (warp >> 1) * 32;

    float acc[4][4][4];
#pragma unroll
    for (int mt = 0; mt < 4; mt++)
#pragma unroll
        for (int nt = 0; nt < 4; nt++)
#pragma unroll
            for (int q = 0; q < 4; q++) acc[mt][nt][q] = 0.f;

    const int ar  = tid >> 2;
    const int akc = (tid & 3) << 2;
    const int bkr = tid >> 5;
    const int bc  = (tid & 31) << 2;

    float4 aS[2], bS[2];

    auto gload = [&](int kt) {
        const int k0 = kt * 16;
#pragma unroll
        for (int h = 0; h < 2; h++) {
            const int row = bm + ar + h * 64;
            const float* ap = (row < splitRow)
                ? (A  + aOff + (long long)row * aRow)
                : (A2 + aOff + (long long)(row - splitRow) * aRow);
            float4 v = *(const float4*)(ap + k0 + akc);
            if (abias) {
                const float4 bb = *(const float4*)(abias + bl * abLo + k0 + akc);
                v.x += bb.x; v.y += bb.y; v.z += bb.z; v.w += bb.w;
            }
            aS[h] = v;
        }
        if (BT) {
#pragma unroll
            for (int h = 0; h < 2; h++) {
                const int nrow = bn + ar + h * 64;
                float4 v = make_float4(0.f, 0.f, 0.f, 0.f);
                if (nrow < N)
                    v = *(const float4*)(B + bOff + (long long)nrow * bRow + k0 + akc);
                bS[h] = v;
            }
        } else {
            const int col = bn + bc;
#pragma unroll
            for (int h = 0; h < 2; h++) {
                float4 v = make_float4(0.f, 0.f, 0.f, 0.f);
                if (col < N)
                    v = *(const float4*)(B + bOff + (long long)(k0 + bkr + h * 8) * bRow + col);
                bS[h] = v;
            }
        }
    };

    auto sstore = [&](int buf) {
#pragma unroll
        for (int h = 0; h < 2; h++) {
            uint32_t* p = &As[buf][(ar + h * 64) * 20 + akc];
            *(uint4*)p = make_uint4(f2tf32(aS[h].x), f2tf32(aS[h].y),
                                    f2tf32(aS[h].z), f2tf32(aS[h].w));
        }
        if (BT) {
#pragma unroll
            for (int h = 0; h < 2; h++) {
                uint32_t* p = &Bs[buf][(ar + h * 64) * 20 + akc];
                *(uint4*)p = make_uint4(f2tf32(bS[h].x), f2tf32(bS[h].y),
                                        f2tf32(bS[h].z), f2tf32(bS[h].w));
            }
        } else {
#pragma unroll
            for (int h = 0; h < 2; h++) {
                uint32_t* p = &Bs[buf][(bkr + h * 8) * 136 + bc];
                *(uint4*)p = make_uint4(f2tf32(bS[h].x), f2tf32(bS[h].y),
                                        f2tf32(bS[h].z), f2tf32(bS[h].w));
            }
        }
    };

    auto compute = [&](int buf) {
#pragma unroll
        for (int kk = 0; kk < 16; kk += 8) {
            uint32_t af[4][4], bf[4][2];
#pragma unroll
            for (int mt = 0; mt < 4; mt++) {
                const int m0 = wm + mt * 16 + lr;
                af[mt][0] = As[buf][m0 * 20 + kk + lc];
                af[mt][1] = As[buf][(m0 + 8) * 20 + kk + lc];
                af[mt][2] = As[buf][m0 * 20 + kk + 4 + lc];
                af[mt][3] = As[buf][(m0 + 8) * 20 + kk + 4 + lc];
            }
#pragma unroll
            for (int nt = 0; nt < 4; nt++) {
                const int n0 = wn + nt * 8 + lr;
                if (BT) {
                    bf[nt][0] = Bs[buf][n0 * 20 + kk + lc];
                    bf[nt][1] = Bs[buf][n0 * 20 + kk + 4 + lc];
                } else {
                    bf[nt][0] = Bs[buf][(kk + lc) * 136 + n0];
                    bf[nt][1] = Bs[buf][(kk + 4 + lc) * 136 + n0];
                }
            }
#pragma unroll
            for (int mt = 0; mt < 4; mt++)
#pragma unroll
                for (int nt = 0; nt < 4; nt++)
                    MMA_TF32(acc[mt][nt], af[mt], bf[nt]);
        }
    };

    const int nk = Kd >> 4;
    gload(0);
    sstore(0);
    __syncthreads();
    for (int kt = 0; kt < nk; kt++) {
        const int buf = kt & 1;
        if (kt + 1 < nk) gload(kt + 1);
        compute(buf);
        if (kt + 1 < nk) sstore(buf ^ 1);
        __syncthreads();
    }

#pragma unroll
    for (int mt = 0; mt < 4; mt++) {
#pragma unroll
        for (int nt = 0; nt < 4; nt++) {
            const int col = bn + wn + nt * 8 + lc * 2;
            if (col >= N) continue;
#pragma unroll
            for (int half = 0; half < 2; half++) {
                const int row = bm + wm + mt * 16 + lr + half * 8;
                float v0 = acc[mt][nt][half * 2 + 0];
                float v1 = acc[mt][nt][half * 2 + 1];
                if (cbias) { v0 += cbias[col]; v1 += cbias[col + 1]; }
                if (resid) {
                    const float* rp = resid + cOff + (long long)row * cRow + col;
                    v0 += rp[0]; v1 += rp[1];
                }
                if (doRelu) { v0 = fmaxf(v0, 0.f); v1 = fmaxf(v1, 0.f); }
                float* cp = C + cOff + (long long)row * cRow + col;
                cp[0] = v0; cp[1] = v1;
            }
        }
    }
}

// ----------------------------------------------------------------------------
// Flash attention: fuses AC-GEMM + rel-shift BD add + mask + online softmax + PV.
// One block per (128-query tile, b*16+n). 8 warps (2x4).
// Smem: Qs/Ks [row][68] tf32, Vs [j][68] tf32, Ss [row][132] (fp32 S then tf32 P).
// ----------------------------------------------------------------------------
#define QSS 68
#define SSS 132
#define FLASH_SMEM ((3 * 128 * QSS + 128 * SSS + 3 * 128) * 4)

__global__ __launch_bounds__(256, 1) void flash_k(
    const float* __restrict__ heads, const float* __restrict__ BD,
    const float* __restrict__ rwb, float* __restrict__ av)
{
    extern __shared__ float sm[];
    float* Qs  = sm;                        // 128*68
    float* Ks  = Qs + 128 * QSS;            // 128*68
    float* Vs  = Ks + 128 * QSS;            // 128*68  ([j][d], row-major)
    float* Ss  = Vs + 128 * QSS;            // 128*132
    float* m_s = Ss + 128 * SSS;            // 128
    float* l_s = m_s + 128;                 // 128
    float* sc_s = l_s + 128;                // 128
    uint32_t* Qsu = (uint32_t*)Qs;
    uint32_t* Ksu = (uint32_t*)Ks;
    uint32_t* Vsu = (uint32_t*)Vs;
    uint32_t* Ssu = (uint32_t*)Ss;

    const int tid = threadIdx.x;
    const int warp = tid >> 5, lane = tid & 31;
    const int lr = lane >> 2, lc = lane & 3;
    const int i0 = blockIdx.x * 128;
    const int bn = blockIdx.y;
    const int b = bn >> 4, n = bn & 15;
    const int wm = (warp & 1) * 64;          // row half (S rows and O rows)
    const int wn = (warp >> 1) * 32;         // S col quarter
    const int wn2 = (warp >> 1) * 16;        // O col quarter

    // ---- load Q tile (+ r_w_bias), convert tf32 ----
    const float* qbase = heads + (size_t)MEMLEN * BSZ * H3;
#pragma unroll
    for (int it = 0; it < 8; it++) {
        const int idx = tid + it * 256;
        const int row = idx >> 4, c4 = (idx & 15) * 4;
        float4 v = *(const float4*)(qbase + ((size_t)(i0 + row) * BSZ + b) * H3 + n * DHEAD + c4);
        const float4 bb = *(const float4*)(rwb + n * DHEAD + c4);
        uint32_t* d = &Qsu[row * QSS + c4];
        d[0] = f2tf32(v.x + bb.x); d[1] = f2tf32(v.y + bb.y);
        d[2] = f2tf32(v.z + bb.z); d[3] = f2tf32(v.w + bb.w);
    }
    if (tid < 128) { m_s[tid] = -1e30f; l_s[tid] = 0.f; }

    float accO[4][2][4];
#pragma unroll
    for (int mt = 0; mt < 4; mt++)
#pragma unroll
        for (int nt = 0; nt < 2; nt++)
#pragma unroll
            for (int q = 0; q < 4; q++) accO[mt][nt][q] = 0.f;

    const int njt = blockIdx.x + 9;          // causal+mem tile bound
    for (int jt = 0; jt < njt; jt++) {
        const int j0 = jt * 128;
        __syncthreads();   // prior PV reads of Ks/Vs/Ss done

        // ---- load K, V tiles ----
#pragma unroll
        for (int it = 0; it < 8; it++) {
            const int idx = tid + it * 256;
            const int row = idx >> 4, c4 = (idx & 15) * 4;
            const float* base = heads + ((size_t)(j0 + row) * BSZ + b) * H3 + n * DHEAD + c4;
            float4 kv = *(const float4*)(base + DMODEL);
            uint32_t* dk = &Ksu[row * QSS + c4];
            dk[0] = f2tf32(kv.x); dk[1] = f2tf32(kv.y);
            dk[2] = f2tf32(kv.z); dk[3] = f2tf32(kv.w);
            float4 vv = *(const float4*)(base + 2 * DMODEL);
            uint32_t* dv = &Vsu[row * QSS + c4];
            dv[0] = f2tf32(vv.x); dv[1] = f2tf32(vv.y);
            dv[2] = f2tf32(vv.z); dv[3] = f2tf32(vv.w);
        }
        __syncthreads();

        // ---- S = Qw . K^T  (128x128, K=64) ----
        float accS[4][4][4];
#pragma unroll
        for (int mt = 0; mt < 4; mt++)
#pragma unroll
            for (int nt = 0; nt < 4; nt++)
#pragma unroll
                for (int q = 0; q < 4; q++) accS[mt][nt][q] = 0.f;

#pragma unroll
        for (int kk = 0; kk < 64; kk += 8) {
            uint32_t af[4][4], bf[4][2];
#pragma unroll
            for (int mt = 0; mt < 4; mt++) {
                const int m0 = wm + mt * 16 + lr;
                af[mt][0] = Qsu[m0 * QSS + kk + lc];
                af[mt][1] = Qsu[(m0 + 8) * QSS + kk + lc];
                af[mt][2] = Qsu[m0 * QSS + kk + 4 + lc];
                af[mt][3] = Qsu[(m0 + 8) * QSS + kk + 4 + lc];
            }
#pragma unroll
            for (int nt = 0; nt < 4; nt++) {
                const int n0 = wn + nt * 8 + lr;
                bf[nt][0] = Ksu[n0 * QSS + kk + lc];
                bf[nt][1] = Ksu[n0 * QSS + kk + 4 + lc];
            }
#pragma unroll
            for (int mt = 0; mt < 4; mt++)
#pragma unroll
                for (int nt = 0; nt < 4; nt++)
                    MMA_TF32(accS[mt][nt], af[mt], bf[nt]);
        }

        // ---- stage raw AC scores to smem ----
#pragma unroll
        for (int mt = 0; mt < 4; mt++) {
            const int r0 = wm + mt * 16 + lr;
#pragma unroll
            for (int nt = 0; nt < 4; nt++) {
                const int col = wn + nt * 8 + 2 * lc;
                *(float2*)&Ss[r0 * SSS + col] =
                    make_float2(accS[mt][nt][0], accS[mt][nt][1]);
                *(float2*)&Ss[(r0 + 8) * SSS + col] =
                    make_float2(accS[mt][nt][2], accS[mt][nt][3]);
            }
        }
        __syncthreads();

        // ---- add shifted BD + mask + scale, online softmax (2 thr / row) ----
        {
            const int row = tid >> 1, half = tid & 1;
            const int i = i0 + row;
            const float* bdrow = BD + ((size_t)bn * QLEN + i) * KLEN + (j0 - i + QLEN - 1);
            const int cbase = half * 64;
            const int vmax = i + MEMLEN - j0;   // valid col c <= vmax
            float mloc = -1e30f;
            float* srow = &Ss[row * SSS + cbase];
            const float* bdp = bdrow + cbase;
#pragma unroll 4
            for (int e = 0; e < 64; e++) {
                const int c = cbase + e;
                float s = (c <= vmax) ? (srow[e] + bdp[e]) * 0.125f : -1e30f;
                srow[e] = s;
                mloc = fmaxf(mloc, s);
            }
            mloc = fmaxf(mloc, __shfl_xor_sync(0xffffffffu, mloc, 1));
            const float mo = m_s[row];
            const float nm = fmaxf(mo, mloc);
            const float alpha = __expf(mo - nm);
            float lsum = 0.f;
            uint32_t* prow = &Ssu[row * SSS + cbase];
#pragma unroll 4
            for (int e = 0; e < 64; e++) {
                const float p = __expf(srow[e] - nm);
                lsum += p;
                prow[e] = f2tf32(p);
            }
            lsum += __shfl_xor_sync(0xffffffffu, lsum, 1);
            if (half == 0) {
                m_s[row] = nm;
                l_s[row] = l_s[row] * alpha + lsum;
                sc_s[row] = alpha;
            }
        }
        __syncthreads();

        // ---- rescale O, then O += P . V  (128x64, K=128) ----
#pragma unroll
        for (int mt = 0; mt < 4; mt++) {
            const int r = wm + mt * 16 + lr;
            const float s0 = sc_s[r], s1 = sc_s[r + 8];
#pragma unroll
            for (int nt = 0; nt < 2; nt++) {
                accO[mt][nt][0] *= s0; accO[mt][nt][1] *= s0;
                accO[mt][nt][2] *= s1; accO[mt][nt][3] *= s1;
            }
        }
#pragma unroll
        for (int jj = 0; jj < 128; jj += 8) {
            uint32_t af[4][4], bf[2][2];
#pragma unroll
            for (int mt = 0; mt < 4; mt++) {
                const int m0 = wm + mt * 16 + lr;
                af[mt][0] = Ssu[m0 * SSS + jj + lc];
                af[mt][1] = Ssu[(m0 + 8) * SSS + jj + lc];
                af[mt][2] = Ssu[m0 * SSS + jj + 4 + lc];
                af[mt][3] = Ssu[(m0 + 8) * SSS + jj + 4 + lc];
            }
#pragma unroll
            for (int nt = 0; nt < 2; nt++) {
                const int n0 = wn2 + nt * 8 + lr;
                bf[nt][0] = Vsu[(jj + lc) * QSS + n0];
                bf[nt][1] = Vsu[(jj + 4 + lc) * QSS + n0];
            }
#pragma unroll
            for (int mt = 0; mt < 4; mt++)
#pragma unroll
                for (int nt = 0; nt < 2; nt++)
                    MMA_TF32(accO[mt][nt], af[mt], bf[nt]);
        }
    }

    // ---- finalize: O /= l, write av[(i*B + b)*D + n*64 + d] ----
    __syncthreads();
#pragma unroll
    for (int mt = 0; mt < 4; mt++) {
        const int r = wm + mt * 16 + lr;
        const float inv0 = 1.f / l_s[r];
        const float inv1 = 1.f / l_s[r + 8];
#pragma unroll
        for (int nt = 0; nt < 2; nt++) {
            const int col = wn2 + nt * 8 + 2 * lc;
            float* p0 = av + ((size_t)(i0 + r) * BSZ + b) * DMODEL + n * DHEAD + col;
            *(float2*)p0 = make_float2(accO[mt][nt][0] * inv0, accO[mt][nt][1] * inv0);
            float* p1 = av + ((size_t)(i0 + r + 8) * BSZ + b) * DMODEL + n * DHEAD + col;
            *(float2*)p1 = make_float2(accO[mt][nt][2] * inv1, accO[mt][nt][3] * inv1);
        }
    }
}

// ----------------------------------------------------------------------------
// Row LayerNorm over D=1024 (one block per row, 4 elems/thread).
// ----------------------------------------------------------------------------
__device__ __forceinline__ float warpSum(float v) {
#pragma unroll
    for (int o = 16; o; o >>= 1) v += __shfl_xor_sync(0xffffffffu, v, o);
    return v;
}

__global__ __launch_bounds__(256) void ln_k(
    const float* __restrict__ X, const float* __restrict__ gam,
    const float* __restrict__ bet, float* __restrict__ Y)
{
    __shared__ float red[8];
    const size_t row = blockIdx.x;
    const int tid = threadIdx.x;
    const float4 v = *(const float4*)(X + row * DMODEL + tid * 4);
    float s = v.x + v.y + v.z + v.w;
    float q = v.x * v.x + v.y * v.y + v.z * v.z + v.w * v.w;

    float ws = warpSum(s);
    if ((tid & 31) == 0) red[tid >> 5] = ws;
    __syncthreads();
    if (tid < 32) {
        float t = (tid < 8) ? red[tid] : 0.f;
        t = warpSum(t);
        if (tid == 0) red[0] = t;
    }
    __syncthreads();
    const float mu = red[0] * (1.f / DMODEL);
    __syncthreads();

    float wq = warpSum(q);
    if ((tid & 31) == 0) red[tid >> 5] = wq;
    __syncthreads();
    if (tid < 32) {
        float t = (tid < 8) ? red[tid] : 0.f;
        t = warpSum(t);
        if (tid == 0) red[0] = t;
    }
    __syncthreads();
    const float var = red[0] * (1.f / DMODEL) - mu * mu;
    const float rs = rsqrtf(var + 1e-5f);

    const float4 gv = *(const float4*)(gam + tid * 4);
    const float4 bv = *(const float4*)(bet + tid * 4);
    float4 o;
    o.x = (v.x - mu) * rs * gv.x + bv.x;
    o.y = (v.y - mu) * rs * gv.y + bv.y;
    o.z = (v.z - mu) * rs * gv.z + bv.z;
    o.w = (v.w - mu) * rs * gv.w + bv.w;
    *(float4*)(Y + row * DMODEL + tid * 4) = o;
}

// ----------------------------------------------------------------------------
extern "C" void kernel_launch(void* const* d_in, const int* in_sizes, int n_in,
                              void* d_out, int out_size)
{
    (void)in_sizes; (void)n_in; (void)out_size;
    const float* w       = (const float*)d_in[0];
    const float* r       = (const float*)d_in[1];
    const float* mems    = (const float*)d_in[2];
    const float* qkv_w   = (const float*)d_in[3];
    const float* r_net_w = (const float*)d_in[4];
    const float* o_w     = (const float*)d_in[5];
    const float* rwb     = (const float*)d_in[6];
    const float* rrb     = (const float*)d_in[7];
    const float* ln1g    = (const float*)d_in[8];
    const float* ln1b    = (const float*)d_in[9];
    const float* ffw1    = (const float*)d_in[10];
    const float* ffb1    = (const float*)d_in[11];
    const float* ffw2    = (const float*)d_in[12];
    const float* ffb2    = (const float*)d_in[13];
    const float* ln2g    = (const float*)d_in[14];
    const float* ln2b    = (const float*)d_in[15];
    float* out = (float*)d_out;

    float *heads, *rk, *BD, *av, *tmp, *out1, *ffh;
    cudaGetSymbolAddress((void**)&heads, g_heads);
    cudaGetSymbolAddress((void**)&rk,    g_rk);
    cudaGetSymbolAddress((void**)&BD,    g_BD);
    cudaGetSymbolAddress((void**)&av,    g_av);
    cudaGetSymbolAddress((void**)&tmp,   g_tmp);
    cudaGetSymbolAddress((void**)&out1,  g_out1);
    cudaGetSymbolAddress((void**)&ffh,   g_ffh);

    static int s_attr_done = 0;
    if (!s_attr_done) {
        cudaFuncSetAttribute(flash_k, cudaFuncAttributeMaxDynamicSharedMemorySize,
                             FLASH_SMEM);
        s_attr_done = 1;
    }

    const dim3 blk(256);
    const int BIG = 1 << 30;
    const float* qbase = heads + (size_t)MEMLEN * BSZ * H3;  // query rows

    // 1) heads = concat(mems, w) @ qkv_w          [8192 x 3072 x 1024]
    mma_gemm<0><<<dim3(H3 / 128, (KLEN * BSZ) / 128, 1), blk>>>(
        mems, w, MEMLEN * BSZ, DMODEL, 0, 0, nullptr, 0,
        qkv_w, H3, 0, 0, nullptr, nullptr, 0,
        heads, H3, 0, 0, KLEN * BSZ, H3, DMODEL);

    // 2) rk = r @ r_net_w                          [2048 x 1024 x 1024]
    mma_gemm<0><<<dim3(DMODEL / 128, KLEN / 128, 1), blk>>>(
        r, r, BIG, DMODEL, 0, 0, nullptr, 0,
        r_net_w, DMODEL, 0, 0, nullptr, nullptr, 0,
        rk, DMODEL, 0, 0, KLEN, DMODEL, DMODEL);

    // 3) BD_pre[bn][i][c] = (q_i + rrb_n) . rk_c   batched, K=64
    mma_gemm<1><<<dim3(KLEN / 128, QLEN / 128, BSZ * NHEAD), blk>>>(
        qbase, qbase, BIG, BSZ * H3, H3, DHEAD, rrb, DHEAD,
        rk, DMODEL, 0, DHEAD, nullptr, nullptr, 0,
        BD, KLEN, 16 * QK, QK, QLEN, KLEN, DHEAD);

    // 4) flash: AC + shifted-BD + mask + softmax + PV -> av
    flash_k<<<dim3(QLEN / 128, BSZ * NHEAD), blk, FLASH_SMEM>>>(heads, BD, rwb, av);

    // 5) attn_out = av @ o_w + w (residual)        [4096 x 1024 x 1024]
    mma_gemm<0><<<dim3(DMODEL / 128, (QLEN * BSZ) / 128, 1), blk>>>(
        av, av, BIG, DMODEL, 0, 0, nullptr, 0,
        o_w, DMODEL, 0, 0, nullptr, w, 0,
        tmp, DMODEL, 0, 0, QLEN * BSZ, DMODEL, DMODEL);

    // 6) LN1
    ln_k<<<QLEN * BSZ, blk>>>(tmp, ln1g, ln1b, out1);

    // 7) ffh = relu(out1 @ ff_w1 + b1)             [4096 x 4096 x 1024]
    mma_gemm<0><<<dim3(DINNER / 128, (QLEN * BSZ) / 128, 1), blk>>>(
        out1, out1, BIG, DMODEL, 0, 0, nullptr, 0,
        ffw1, DINNER, 0, 0, ffb1, nullptr, 1,
        ffh, DINNER, 0, 0, QLEN * BSZ, DINNER, DMODEL);

    // 8) tmp = ffh @ ff_w2 + b2 + out1             [4096 x 1024 x 4096]
    mma_gemm<0><<<dim3(DMODEL / 128, (QLEN * BSZ) / 128, 1), blk>>>(
        ffh, ffh, BIG, DINNER, 0, 0, nullptr, 0,
        ffw2, DMODEL, 0, 0, ffb2, out1, 0,
        tmp, DMODEL, 0, 0, QLEN * BSZ, DMODEL, DINNER);

    // 9) LN2 -> output
    ln_k<<<QLEN * BSZ, blk>>>(tmp, ln2g, ln2b, out);
}